// round 4
// baseline (speedup 1.0000x reference)
#include <cuda_runtime.h>

#define BB 128  // batch
#define BV 32   // batch in float4 units (logic layers)
#define BH 64   // batch in float2 units (conv layers)

// ---------------- padded geometry (halos stay zero: never written) ---------
__device__ __align__(16) float g_bin[9 * 34 * 34 * BB];
__device__ __align__(16) float g_h1[32 * 18 * 18 * BB];
__device__ __align__(16) float g_h2[128 * 10 * 10 * BB];
__device__ __align__(16) float g_h3[512 * 6 * 6 * BB];
__device__ __align__(16) float g_h4[4096 * BB];
__device__ __align__(16) float g_g1[40960 * BB];
__device__ __align__(16) float g_g2[20480 * BB];
__device__ __align__(16) float g_mix[83552 * 4];
__device__ __align__(16) float g_part[160 * BB];

__constant__ float GC[64] = {
    0, 0, 0, 0,   0, 0, 0, 1,   0, 1, 0, -1,  0, 1, 0, 0,
    0, 0, 1, -1,  0, 0, 1, 0,   0, 1, 1, -2,  0, 1, 1, -1,
    1, -1, -1, 1, 1, -1, -1, 2, 1, 0, -1, 0,  1, 0, -1, 1,
    1, -1, 0, 0,  1, -1, 0, 1,  1, 0, 0, -1,  1, 0, 0, 0};

#define OFF_C1 0
#define OFF_C2 224
#define OFF_C3 1120
#define OFF_C4 4704
#define OFF_L1 11872
#define OFF_L2 52832
#define OFF_L3 73312
#define N_NODES 83552

// ---------------- helpers ----------------
__device__ __forceinline__ float4 f4(float v) { return make_float4(v, v, v, v); }
__device__ __forceinline__ float4 gate4v(float4 a, float4 b, float w0, float w1, float w2, float w3) {
    float4 r;
    r.x = fmaf(w3, a.x * b.x, fmaf(w2, b.x, fmaf(w1, a.x, w0)));
    r.y = fmaf(w3, a.y * b.y, fmaf(w2, b.y, fmaf(w1, a.y, w0)));
    r.z = fmaf(w3, a.z * b.z, fmaf(w2, b.z, fmaf(w1, a.z, w0)));
    r.w = fmaf(w3, a.w * b.w, fmaf(w2, b.w, fmaf(w1, a.w, w0)));
    return r;
}
__device__ __forceinline__ float2 gate2v(float2 a, float2 b, float w0, float w1, float w2, float w3) {
    float2 r;
    r.x = fmaf(w3, a.x * b.x, fmaf(w2, b.x, fmaf(w1, a.x, w0)));
    r.y = fmaf(w3, a.y * b.y, fmaf(w2, b.y, fmaf(w1, a.y, w0)));
    return r;
}

// ---------------- kernel 1: gate mixing ----------------
__global__ void mix_kernel(const float* __restrict__ s0, const float* __restrict__ s1,
                           const float* __restrict__ s2, const float* __restrict__ s3,
                           const float* __restrict__ s4, const float* __restrict__ s5,
                           const float* __restrict__ s6, float* __restrict__ dst) {
    int tid = blockIdx.x * blockDim.x + threadIdx.x;
    if (tid >= N_NODES) return;
    const int offs[8] = {OFF_C1, OFF_C2, OFF_C3, OFF_C4, OFF_L1, OFF_L2, OFF_L3, N_NODES};
    const float* srcs[7] = {s0, s1, s2, s3, s4, s5, s6};
    int seg = 0;
    while (tid >= offs[seg + 1]) seg++;
    const float* w = srcs[seg] + (size_t)(tid - offs[seg]) * 16;

    float e[16];
    float mx = w[0];
#pragma unroll
    for (int i = 1; i < 16; i++) mx = fmaxf(mx, w[i]);
    float s = 0.f;
#pragma unroll
    for (int i = 0; i < 16; i++) { e[i] = __expf(w[i] - mx); s += e[i]; }
    float inv = 1.f / s;
    float m0 = 0.f, m1 = 0.f, m2 = 0.f, m3 = 0.f;
#pragma unroll
    for (int i = 0; i < 16; i++) {
        float p = e[i] * inv;
        m0 = fmaf(p, GC[i * 4 + 0], m0);
        m1 = fmaf(p, GC[i * 4 + 1], m1);
        m2 = fmaf(p, GC[i * 4 + 2], m2);
        m3 = fmaf(p, GC[i * 4 + 3], m3);
    }
    float4 o; o.x = m0; o.y = m1; o.z = m2; o.w = m3;
    ((float4*)dst)[tid] = o;
}

// ---------------- kernel 2: binarize + BCHW -> CHWB (padded out) -----------
__global__ void binarize_kernel(const float* __restrict__ x, float* __restrict__ bin) {
    __shared__ float tile[32][33];
    int c = blockIdx.z;
    int h = blockIdx.y;
    int bc = blockIdx.x;
    int b = bc * 32 + threadIdx.y;
    tile[threadIdx.y][threadIdx.x] = x[(((size_t)b * 3 + c) * 32 + h) * 32 + threadIdx.x];
    __syncthreads();
    int w = threadIdx.y;
    int bout = bc * 32 + threadIdx.x;
    float v = tile[threadIdx.x][w];
    const float thr[3] = {0.25f, 0.5f, 0.75f};
#pragma unroll
    for (int t = 0; t < 3; t++) {
        size_t idx = (((size_t)(t * 3 + c)) * 34 * 34 + (size_t)(h + 1) * 34 + (w + 1)) * BB + bout;
        bin[idx] = (v > thr[t]) ? 1.f : 0.f;
    }
}

// ---------------- tree_conv + or_pool: float2 lanes, 64 threads/(o,s) ------
template <int Hin, int SPB, bool PADOUT>
__global__ void __launch_bounds__(64 * SPB, 6) tree_conv_kernel(
    const float2* __restrict__ in, float2* __restrict__ out,
    const int* __restrict__ leaf, const float* __restrict__ mix) {
    constexpr int Win = Hin + 2;
    constexpr int Wo = Hin / 2;
    constexpr int Wop = PADOUT ? (Wo + 2) : Wo;
    int o = blockIdx.y;
    __shared__ float sm[28];
    __shared__ int soff[8];  // per-leaf element offset (float2 units)
    int t = threadIdx.y * 64 + threadIdx.x;
    if (t < 28) sm[t] = mix[o * 28 + t];
    if (t < 8) {
        int idx = leaf[o * 8 + t];
        int ch = idx / 9, p = idx % 9;
        int dy = p / 3, dx = p % 3;
        soff[t] = (ch * Win * Win + dy * Win + dx) * BH;
    }
    __syncthreads();
    int s = blockIdx.x * SPB + threadIdx.y;
    int wo = s % Wo, ho = s / Wo;
    int lane = threadIdx.x;  // 0..63 batch float2 lane

    float2 r = make_float2(-1e30f, -1e30f);
#pragma unroll
    for (int ph = 0; ph < 2; ph++) {
#pragma unroll
        for (int pw = 0; pw < 2; pw++) {
            int pos = ((2 * ho + ph) * Win + (2 * wo + pw)) * BH + lane;
            float2 v[8];
#pragma unroll
            for (int l = 0; l < 8; l++) v[l] = in[soff[l] + pos];
            float2 t0 = gate2v(v[0], v[1], sm[0], sm[1], sm[2], sm[3]);
            float2 t1 = gate2v(v[2], v[3], sm[4], sm[5], sm[6], sm[7]);
            float2 t2 = gate2v(v[4], v[5], sm[8], sm[9], sm[10], sm[11]);
            float2 t3 = gate2v(v[6], v[7], sm[12], sm[13], sm[14], sm[15]);
            float2 u0 = gate2v(t0, t1, sm[16], sm[17], sm[18], sm[19]);
            float2 u1 = gate2v(t2, t3, sm[20], sm[21], sm[22], sm[23]);
            float2 z  = gate2v(u0, u1, sm[24], sm[25], sm[26], sm[27]);
            r.x = fmaxf(r.x, z.x);
            r.y = fmaxf(r.y, z.y);
        }
    }
    size_t oidx;
    if (PADOUT)
        oidx = ((size_t)o * Wop * Wop + (size_t)(ho + 1) * Wop + (wo + 1)) * BH + lane;
    else
        oidx = ((size_t)o * Wo * Wo + (size_t)ho * Wo + wo) * BH + lane;
    out[oidx] = r;
}

// ---------------- logic layers (float4 lanes) ----------------
__global__ void logic_kernel(const float4* __restrict__ in, float4* __restrict__ out,
                             const int* __restrict__ ai, const int* __restrict__ bi,
                             const float4* __restrict__ mix, int Dout) {
    int tid = blockIdx.x * blockDim.x + threadIdx.x;
    if (tid >= Dout * BV) return;
    int j = tid >> 5, lane = tid & 31;
    float4 w = mix[j];
    float4 a = in[(size_t)__ldg(&ai[j]) * BV + lane];
    float4 b = in[(size_t)__ldg(&bi[j]) * BV + lane];
    out[tid] = gate4v(a, b, w.x, w.y, w.z, w.w);
}

// ---------------- logic3 fused with group-sum partials (4 warps/block) -----
__global__ void __launch_bounds__(128) logic3_sum_kernel(
    const float4* __restrict__ in, float4* __restrict__ part,
    const int* __restrict__ ai, const int* __restrict__ bi,
    const float4* __restrict__ mix) {
    __shared__ float4 red[4][32];
    int blk = blockIdx.x;
    int wz = threadIdx.y;
    int lane = threadIdx.x;
    int j0 = blk * 64 + wz * 16;
    float4 acc = f4(0.f);
#pragma unroll
    for (int jj = 0; jj < 16; jj++) {
        int j = j0 + jj;
        float4 w = mix[j];
        float4 a = in[(size_t)__ldg(&ai[j]) * BV + lane];
        float4 b = in[(size_t)__ldg(&bi[j]) * BV + lane];
        float4 g = gate4v(a, b, w.x, w.y, w.z, w.w);
        acc.x += g.x; acc.y += g.y; acc.z += g.z; acc.w += g.w;
    }
    red[wz][lane] = acc;
    __syncthreads();
    if (wz == 0) {
        float4 s = red[0][lane], s1 = red[1][lane], s2 = red[2][lane], s3 = red[3][lane];
        s.x += s1.x + s2.x + s3.x;
        s.y += s1.y + s2.y + s3.y;
        s.z += s1.z + s2.z + s3.z;
        s.w += s1.w + s2.w + s3.w;
        part[(size_t)blk * BV + lane] = s;
    }
}

// ---------------- final reduce ----------------
__global__ void final_sum_kernel(const float* __restrict__ part, float* __restrict__ out) {
    int tid = blockIdx.x * blockDim.x + threadIdx.x;
    if (tid >= 1280) return;
    int cls = tid >> 7, b = tid & 127;
    float s = 0.f;
#pragma unroll
    for (int k = 0; k < 16; k++) s += part[(size_t)(cls * 16 + k) * BB + b];
    out[b * 10 + cls] = s * 0.01f;
}

// ---------------- host launcher ----------------
extern "C" void kernel_launch(void* const* d_in, const int* in_sizes, int n_in,
                              void* d_out, int out_size) {
    const float* x   = (const float*)d_in[0];
    const int*   c1i = (const int*)d_in[1];  const float* c1w = (const float*)d_in[2];
    const int*   c2i = (const int*)d_in[3];  const float* c2w = (const float*)d_in[4];
    const int*   c3i = (const int*)d_in[5];  const float* c3w = (const float*)d_in[6];
    const int*   c4i = (const int*)d_in[7];  const float* c4w = (const float*)d_in[8];
    const int*   l1a = (const int*)d_in[9];  const int* l1b = (const int*)d_in[10];
    const float* l1w = (const float*)d_in[11];
    const int*   l2a = (const int*)d_in[12]; const int* l2b = (const int*)d_in[13];
    const float* l2w = (const float*)d_in[14];
    const int*   l3a = (const int*)d_in[15]; const int* l3b = (const int*)d_in[16];
    const float* l3w = (const float*)d_in[17];

    float *bin, *h1, *h2, *h3, *h4, *g1, *g2, *mixb, *part;
    cudaGetSymbolAddress((void**)&bin,  g_bin);
    cudaGetSymbolAddress((void**)&h1,   g_h1);
    cudaGetSymbolAddress((void**)&h2,   g_h2);
    cudaGetSymbolAddress((void**)&h3,   g_h3);
    cudaGetSymbolAddress((void**)&h4,   g_h4);
    cudaGetSymbolAddress((void**)&g1,   g_g1);
    cudaGetSymbolAddress((void**)&g2,   g_g2);
    cudaGetSymbolAddress((void**)&mixb, g_mix);
    cudaGetSymbolAddress((void**)&part, g_part);

    mix_kernel<<<(N_NODES + 127) / 128, 128>>>(c1w, c2w, c3w, c4w, l1w, l2w, l3w, mixb);
    binarize_kernel<<<dim3(4, 32, 3), dim3(32, 32)>>>(x, bin);

    // float2 lanes: blockDim (64, SPB)
    tree_conv_kernel<32, 4, true> <<<dim3(64, 32),  dim3(64, 4)>>>((const float2*)bin, (float2*)h1, c1i, mixb + OFF_C1 * 4);
    tree_conv_kernel<16, 4, true> <<<dim3(16, 128), dim3(64, 4)>>>((const float2*)h1,  (float2*)h2, c2i, mixb + OFF_C2 * 4);
    tree_conv_kernel<8, 4, true>  <<<dim3(4, 512),  dim3(64, 4)>>>((const float2*)h2,  (float2*)h3, c3i, mixb + OFF_C3 * 4);
    tree_conv_kernel<4, 4, false><<<dim3(1, 1024), dim3(64, 4)>>>((const float2*)h3,  (float2*)h4, c4i, mixb + OFF_C4 * 4);

    logic_kernel<<<(40960 * BV) / 256, 256>>>((const float4*)h4, (float4*)g1, l1a, l1b, (const float4*)(mixb + OFF_L1 * 4), 40960);
    logic_kernel<<<(20480 * BV) / 256, 256>>>((const float4*)g1, (float4*)g2, l2a, l2b, (const float4*)(mixb + OFF_L2 * 4), 20480);
    logic3_sum_kernel<<<160, dim3(32, 4)>>>((const float4*)g2, (float4*)part, l3a, l3b, (const float4*)(mixb + OFF_L3 * 4));
    final_sum_kernel<<<10, 128>>>(part, (float*)d_out);
}